// round 1
// baseline (speedup 1.0000x reference)
#include <cuda_runtime.h>
#include <cuda_bf16.h>
#include <cstddef>

// Problem constants
#define B_   64
#define S_   1024
#define E_   300
#define NGR_ 5
#define Wn_  1020            // S - (N-1)
#define H0_  512
#define H1_  256
#define H2_  128
#define M_   (B_*Wn_)        // 65280
#define KS_  (NGR_*E_)       // 1500

// GEMM tiling
#define BM 128
#define BN 128
#define BK 16
#define TM 8
#define TN 8
// 256 threads, each computes TM x TN

// Scratch (device globals — no allocation allowed)
__device__ float g_h0[(size_t)M_ * H0_];   // 133.7 MB
__device__ float g_h1[(size_t)M_ * H1_];   //  66.8 MB
__device__ float g_h2[(size_t)M_ * H2_];   //  33.4 MB

// ---------------------------------------------------------------------------
// Kernel 1: fused embedding-gather sliding-window GEMM
//   h0[m, n] = sum_k table[x[b, w + k/E]][k%E] * W_slide[k, n] + b_slide[n]
//   m = b*Wn + w ;  M=65280, N=512, K=1500
// ---------------------------------------------------------------------------
__global__ void __launch_bounds__(256)
gemm_slide(const int* __restrict__ x, const float* __restrict__ table,
           const float* __restrict__ Wsl, const float* __restrict__ bsl)
{
    __shared__ float As[BK][BM + 4];
    __shared__ float Bs[BK][BN];

    const int tid = threadIdx.x;
    const int tx = tid & 15;          // 0..15  (N direction)
    const int ty = tid >> 4;          // 0..15  (M direction)
    const int m0 = blockIdx.x * BM;
    const int n0 = blockIdx.y * BN;

    // A-load mapping: column c = tid&15, rows la_r0 .. la_r0+7
    const int la_c  = tid & 15;
    const int la_r0 = (tid >> 4) * 8;
    // B-load mapping: row kr = tid>>4, cols lb_n .. lb_n+7
    const int lb_k = tid >> 4;
    const int lb_n = (tid & 15) * 8;

    // Precompute token bases for this thread's 8 A-rows (fixed across k loop)
    int xbase[8];
#pragma unroll
    for (int i = 0; i < 8; i++) {
        int m = m0 + la_r0 + i;
        int b = m / Wn_;
        int w = m - b * Wn_;
        xbase[i] = b * S_ + w;
    }

    float acc[TM][TN];
#pragma unroll
    for (int i = 0; i < TM; i++)
#pragma unroll
        for (int j = 0; j < TN; j++) acc[i][j] = 0.f;

    for (int k0 = 0; k0 < KS_; k0 += BK) {
        // ---- load A tile (gathered) ----
        {
            int k = k0 + la_c;
            if (k < KS_) {
                int j = k / E_;
                int e = k - j * E_;
#pragma unroll
                for (int i = 0; i < 8; i++) {
                    int tok = __ldg(&x[xbase[i] + j]);
                    As[la_c][la_r0 + i] = table[(size_t)tok * E_ + e];
                }
            } else {
#pragma unroll
                for (int i = 0; i < 8; i++) As[la_c][la_r0 + i] = 0.f;
            }
        }
        // ---- load B tile ----
        {
            int kb = k0 + lb_k;
            if (kb < KS_) {
                const float* src = Wsl + (size_t)kb * H0_ + n0 + lb_n;
                float4 v0 = *(const float4*)(src);
                float4 v1 = *(const float4*)(src + 4);
                *(float4*)&Bs[lb_k][lb_n]     = v0;
                *(float4*)&Bs[lb_k][lb_n + 4] = v1;
            } else {
#pragma unroll
                for (int i = 0; i < 8; i++) Bs[lb_k][lb_n + i] = 0.f;
            }
        }
        __syncthreads();

#pragma unroll
        for (int kk = 0; kk < BK; kk++) {
            float a[TM], b[TN];
#pragma unroll
            for (int i = 0; i < TM; i++) a[i] = As[kk][ty * TM + i];
#pragma unroll
            for (int j = 0; j < TN; j++) b[j] = Bs[kk][tx * TN + j];
#pragma unroll
            for (int i = 0; i < TM; i++)
#pragma unroll
                for (int j = 0; j < TN; j++) acc[i][j] += a[i] * b[j];
        }
        __syncthreads();
    }

    // Epilogue: + bias, no activation on slide layer
#pragma unroll
    for (int i = 0; i < TM; i++) {
        int m = m0 + ty * TM + i;
#pragma unroll
        for (int j = 0; j < TN; j++) {
            int n = n0 + tx * TN + j;
            g_h0[(size_t)m * H0_ + n] = acc[i][j] + bsl[n];
        }
    }
}

// ---------------------------------------------------------------------------
// Kernel 2/3: plain GEMM  C[m,n] = act(A[m,:K] @ Bm[:K,n] + bias[n])
//   K and N are multiples of 16/128 respectively for the layers we use.
// ---------------------------------------------------------------------------
__global__ void __launch_bounds__(256)
gemm_plain(const float* __restrict__ A, const float* __restrict__ Bm,
           const float* __restrict__ bias, float* __restrict__ C,
           int K, int Nn, int relu)
{
    __shared__ float As[BK][BM + 4];
    __shared__ float Bs[BK][BN];

    const int tid = threadIdx.x;
    const int tx = tid & 15;
    const int ty = tid >> 4;
    const int m0 = blockIdx.x * BM;
    const int n0 = blockIdx.y * BN;

    const int la_c  = tid & 15;
    const int la_r0 = (tid >> 4) * 8;
    const int lb_k = tid >> 4;
    const int lb_n = (tid & 15) * 8;

    float acc[TM][TN];
#pragma unroll
    for (int i = 0; i < TM; i++)
#pragma unroll
        for (int j = 0; j < TN; j++) acc[i][j] = 0.f;

    for (int k0 = 0; k0 < K; k0 += BK) {
        {
            int k = k0 + la_c;   // K is a multiple of BK for our layers
#pragma unroll
            for (int i = 0; i < 8; i++) {
                int m = m0 + la_r0 + i;
                As[la_c][la_r0 + i] = A[(size_t)m * K + k];
            }
        }
        {
            int kb = k0 + lb_k;
            const float* src = Bm + (size_t)kb * Nn + n0 + lb_n;
            float4 v0 = *(const float4*)(src);
            float4 v1 = *(const float4*)(src + 4);
            *(float4*)&Bs[lb_k][lb_n]     = v0;
            *(float4*)&Bs[lb_k][lb_n + 4] = v1;
        }
        __syncthreads();

#pragma unroll
        for (int kk = 0; kk < BK; kk++) {
            float a[TM], b[TN];
#pragma unroll
            for (int i = 0; i < TM; i++) a[i] = As[kk][ty * TM + i];
#pragma unroll
            for (int j = 0; j < TN; j++) b[j] = Bs[kk][tx * TN + j];
#pragma unroll
            for (int i = 0; i < TM; i++)
#pragma unroll
                for (int j = 0; j < TN; j++) acc[i][j] += a[i] * b[j];
        }
        __syncthreads();
    }

#pragma unroll
    for (int i = 0; i < TM; i++) {
        int m = m0 + ty * TM + i;
#pragma unroll
        for (int j = 0; j < TN; j++) {
            int n = n0 + tx * TN + j;
            float v = acc[i][j] + bias[n];
            if (relu) v = fmaxf(v, 0.f);
            C[(size_t)m * Nn + n] = v;
        }
    }
}

// ---------------------------------------------------------------------------
// Kernel 4: ragged masked mean-pool over windows
//   out[b, h] = (1/valid_b) * sum_{w < valid_b} h2[b, w, h],  valid_b = len_b-4
// ---------------------------------------------------------------------------
__global__ void __launch_bounds__(512)
pool_kernel(const int* __restrict__ lengths, float* __restrict__ out)
{
    __shared__ float red[512];
    const int b = blockIdx.x;
    const int tid = threadIdx.x;
    const int h = tid & 127;
    const int slice = tid >> 7;      // 0..3
    const int valid = lengths[b] - (NGR_ - 1);

    float s = 0.f;
    const float* p = g_h2 + (size_t)b * Wn_ * H2_ + h;
    for (int w = slice; w < valid; w += 4)
        s += p[(size_t)w * H2_];

    red[tid] = s;
    __syncthreads();
    if (slice == 0) {
        float tot = red[h] + red[h + 128] + red[h + 256] + red[h + 384];
        out[b * H2_ + h] = tot / (float)valid;
    }
}

// ---------------------------------------------------------------------------
extern "C" void kernel_launch(void* const* d_in, const int* in_sizes, int n_in,
                              void* d_out, int out_size)
{
    const int*   x       = (const int*)  d_in[0];
    const int*   lengths = (const int*)  d_in[1];
    const float* table   = (const float*)d_in[2];
    const float* Wsl     = (const float*)d_in[3];
    const float* bsl     = (const float*)d_in[4];
    const float* W1      = (const float*)d_in[5];
    const float* b1      = (const float*)d_in[6];
    const float* W2      = (const float*)d_in[7];
    const float* b2      = (const float*)d_in[8];
    float*       out     = (float*)d_out;

    // Resolve device-global scratch addresses (no allocation, capture-safe)
    float *h0p, *h1p, *h2p;
    cudaGetSymbolAddress((void**)&h0p, g_h0);
    cudaGetSymbolAddress((void**)&h1p, g_h1);
    cudaGetSymbolAddress((void**)&h2p, g_h2);

    dim3 blk(256);

    // Layer 0: fused gather GEMM  [65280,1500] x [1500,512]
    dim3 gA(M_ / BM, H0_ / BN);
    gemm_slide<<<gA, blk>>>(x, table, Wsl, bsl);

    // Layer 1: relu(h0 @ W1 + b1)  [65280,512] x [512,256]
    dim3 gB(M_ / BM, H1_ / BN);
    gemm_plain<<<gB, blk>>>(h0p, W1, b1, h1p, H0_, H1_, 1);

    // Layer 2: relu(h1 @ W2 + b2)  [65280,256] x [256,128]
    dim3 gC(M_ / BM, H2_ / BN);
    gemm_plain<<<gC, blk>>>(h1p, W2, b2, h2p, H1_, H2_, 1);

    // Ragged mean pool -> out [64,128]
    pool_kernel<<<B_, 512>>>(lengths, out);
}

// round 3
// speedup vs baseline: 2.4278x; 2.4278x over previous
#include <cuda_runtime.h>
#include <cuda_fp16.h>
#include <cstdint>
#include <cstddef>

// ---------------- problem constants ----------------
#define B_   64
#define S_   1024
#define E_   300
#define Wn_  1020
#define H0_  512
#define H1_  256
#define H2_  128
#define M_   (B_*Wn_)      // 65280
#define K0P  1536          // layer-0 K (1500) padded to 64

// ---------------- scratch (device globals) ----------------
__device__ __half g_emb_hi[(size_t)(B_*S_+8)*E_];
__device__ __half g_emb_lo[(size_t)(B_*S_+8)*E_];
__device__ __half g_w0hi[H0_*K0P], g_w0lo[H0_*K0P];
__device__ __half g_w1hi[H1_*H0_], g_w1lo[H1_*H0_];
__device__ __half g_w2hi[H2_*H1_], g_w2lo[H2_*H1_];
__device__ __half g_h0hi[(size_t)M_*H0_], g_h0lo[(size_t)M_*H0_];
__device__ __half g_h1hi[(size_t)M_*H1_], g_h1lo[(size_t)M_*H1_];
__device__ float g_h2[(size_t)M_*H2_];
__device__ float g_pool[B_*8*H2_];

// ---------------- asm helpers (all plain sm_80+ features) ----------------
__device__ __forceinline__ uint32_t smem_u32(const void* p) {
    uint32_t a;
    asm("{ .reg .u64 t; cvta.to.shared.u64 t, %1; cvt.u32.u64 %0, t; }" : "=r"(a) : "l"(p));
    return a;
}
__device__ __forceinline__ void cpa8(uint32_t s, const void* g) {
    asm volatile("cp.async.ca.shared.global [%0], [%1], 8;" :: "r"(s), "l"(g));
}
__device__ __forceinline__ void cpa16(uint32_t s, const void* g) {
    asm volatile("cp.async.cg.shared.global [%0], [%1], 16;" :: "r"(s), "l"(g));
}
__device__ __forceinline__ void cp_commit() { asm volatile("cp.async.commit_group;"); }
template<int N> __device__ __forceinline__ void cp_wait() {
    asm volatile("cp.async.wait_group %0;" :: "n"(N));
}
__device__ __forceinline__ void ldm_x4(uint32_t a, uint32_t& r0, uint32_t& r1, uint32_t& r2, uint32_t& r3) {
    asm volatile("ldmatrix.sync.aligned.m8n8.x4.shared.b16 {%0,%1,%2,%3}, [%4];"
                 : "=r"(r0), "=r"(r1), "=r"(r2), "=r"(r3) : "r"(a));
}
__device__ __forceinline__ void ldm_x2(uint32_t a, uint32_t& r0, uint32_t& r1) {
    asm volatile("ldmatrix.sync.aligned.m8n8.x2.shared.b16 {%0,%1}, [%2];"
                 : "=r"(r0), "=r"(r1) : "r"(a));
}
__device__ __forceinline__ void mma16816(float* c, const uint32_t* a, const uint32_t* b) {
    asm volatile("mma.sync.aligned.m16n8k16.row.col.f32.f16.f16.f32 "
                 "{%0,%1,%2,%3}, {%4,%5,%6,%7}, {%8,%9}, {%0,%1,%2,%3};"
                 : "+f"(c[0]), "+f"(c[1]), "+f"(c[2]), "+f"(c[3])
                 : "r"(a[0]), "r"(a[1]), "r"(a[2]), "r"(a[3]), "r"(b[0]), "r"(b[1]));
}

// ---------------- prep kernels ----------------
__global__ void prep_emb(const int* __restrict__ x, const float* __restrict__ table) {
    int idx = blockIdx.x * 256 + threadIdx.x;
    const int total = (B_ * S_ + 8) * E_;
    if (idx >= total) return;
    int row = idx / E_;
    int e = idx - row * E_;
    float v = 0.f;
    if (row < B_ * S_) {
        int tok = x[row];
        v = table[(size_t)tok * E_ + e];
    }
    __half hi = __float2half_rn(v);
    __half lo = __float2half_rn(v - __half2float(hi));
    g_emb_hi[idx] = hi; g_emb_lo[idx] = lo;
}

__global__ void prep_w(const float* __restrict__ W, __half* __restrict__ Thi,
                       __half* __restrict__ Tlo, int K, int Kpad, int Nn) {
    int idx = blockIdx.x * 256 + threadIdx.x;
    if (idx >= Nn * Kpad) return;
    int n = idx / Kpad;
    int k = idx - n * Kpad;
    float v = (k < K) ? W[(size_t)k * Nn + n] : 0.f;   // transpose to [n][k]
    __half hi = __float2half_rn(v);
    __half lo = __float2half_rn(v - __half2float(hi));
    Thi[idx] = hi; Tlo[idx] = lo;
}

// ---------------- HMMA fp16x2-split GEMM ----------------
// CTA 128x128, warps 2(m) x 4(n), warp tile 64x32, BK=32, 3 cp.async stages.
// C = act( [Ah+Al] @ [Bh+Bl]^T + bias ), 3 mma combos (drop lo*lo).
// B given transposed: Bt[n][Kpad]. A row-major [m][K] or window view into emb.
template<bool WIN>
__global__ void __launch_bounds__(256, 1)
gemm_hmma(const __half* __restrict__ Ahg, const __half* __restrict__ Alg,
          const __half* __restrict__ Bhg, const __half* __restrict__ Blg,
          const float* __restrict__ bias,
          __half* __restrict__ Chi, __half* __restrict__ Clo,
          float* __restrict__ Cf,
          int K, int Nn, int relu)
{
    constexpr int RS   = 40;            // smem row stride (halfs): conflict-free for ldmatrix
    constexpr int PART = 128 * RS;      // one operand part (halfs)
    constexpr int STG  = 4 * PART;      // Ah,Al,Bh,Bl
    constexpr int NCA  = WIN ? 8 : 4;   // A chunks per thread (8B or 16B)

    extern __shared__ __half sm[];
    const uint32_t smb = smem_u32(sm);

    const int tid  = threadIdx.x;
    const int lane = tid & 31;
    const int wid  = tid >> 5;
    const int wm   = wid & 1;           // 0..1
    const int wn   = wid >> 1;          // 0..3
    const int m0   = blockIdx.x * 128;
    const int n0   = blockIdx.y * 128;
    const int niter = K >> 5;

    // ---- precompute per-thread load descriptors ----
    // A chunks: WIN: 2048 x 8B chunks; else 1024 x 16B chunks
    const __half* aptr[NCA];
    uint32_t asmoff[NCA];               // smem offset in halfs (stage-invariant)
    {
        const int CS  = WIN ? 4 : 8;    // chunk size halfs
        const int CPR = 32 / CS;        // chunks per row
#pragma unroll
        for (int t = 0; t < NCA; ++t) {
            int idx  = tid + t * 256;
            int part = idx / (128 * CPR);
            int rem  = idx - part * (128 * CPR);
            int row  = rem / CPR;
            int c    = rem - row * CPR;
            size_t rb;
            if (WIN) {
                int m = m0 + row;
                int b = m / Wn_;
                int w = m - b * Wn_;
                rb = (size_t)(b * S_ + w) * E_;
            } else {
                rb = (size_t)(m0 + row) * K;
            }
            aptr[t]   = (part ? Alg : Ahg) + rb + c * CS;
            asmoff[t] = part * PART + row * RS + c * CS;
        }
    }
    // B chunks: 1024 x 16B
    const __half* bptr[4];
    uint32_t bsmoff[4];
#pragma unroll
    for (int t = 0; t < 4; ++t) {
        int idx  = tid + t * 256;
        int part = idx / 512;
        int rem  = idx - part * 512;
        int row  = rem >> 2;
        int c    = rem & 3;
        bptr[t]   = (part ? Blg : Bhg) + (size_t)(n0 + row) * K + c * 8;
        bsmoff[t] = 2 * PART + part * PART + row * RS + c * 8;
    }

    auto load_stage = [&](int stage, int k0) {
        uint32_t sb = smb + 2 * (uint32_t)(stage * STG);
#pragma unroll
        for (int t = 0; t < NCA; ++t) {
            if (WIN) cpa8(sb + 2 * asmoff[t], aptr[t] + k0);
            else     cpa16(sb + 2 * asmoff[t], aptr[t] + k0);
        }
#pragma unroll
        for (int t = 0; t < 4; ++t)
            cpa16(sb + 2 * bsmoff[t], bptr[t] + k0);
        cp_commit();
    };

    // ---- fragment addressing (stage-invariant parts) ----
    // A: row = wm*64 + i*16 + lane%16 ; col = ks*16 + (lane>>4)*8
    const uint32_t a_row = wm * 64 + (lane & 15);
    const uint32_t a_col = (lane >> 4) * 8;
    // B: row n = wn*32 + j*8 + lane%8 ; col = ks*16 + ((lane>>3)&1)*8 (lanes>=16 mirror)
    const uint32_t b_row = wn * 32 + (lane & 7);
    const uint32_t b_col = ((lane >> 3) & 1) * 8;

    float acc[4][4][4];
#pragma unroll
    for (int i = 0; i < 4; ++i)
#pragma unroll
        for (int j = 0; j < 4; ++j)
#pragma unroll
            for (int q = 0; q < 4; ++q) acc[i][j][q] = 0.f;

    // ---- pipeline ----
    load_stage(0, 0);
    load_stage(1, 32);

    for (int it = 0; it < niter; ++it) {
        if (it + 1 < niter) cp_wait<1>(); else cp_wait<0>();
        __syncthreads();
        if (it + 2 < niter) load_stage((it + 2) % 3, (it + 2) * 32);

        const uint32_t sb = smb + 2 * (uint32_t)((it % 3) * STG);
#pragma unroll
        for (int ks = 0; ks < 2; ++ks) {
            uint32_t ah[4][4], al[4][4], bh[4][2], bl[4][2];
#pragma unroll
            for (int i = 0; i < 4; ++i) {
                uint32_t off = (a_row + i * 16) * RS + (ks * 16 + a_col);
                ldm_x4(sb + 2 * off,          ah[i][0], ah[i][1], ah[i][2], ah[i][3]);
                ldm_x4(sb + 2 * (off + PART), al[i][0], al[i][1], al[i][2], al[i][3]);
            }
#pragma unroll
            for (int j = 0; j < 4; ++j) {
                uint32_t off = 2 * PART + (b_row + j * 8) * RS + (ks * 16 + b_col);
                ldm_x2(sb + 2 * off,          bh[j][0], bh[j][1]);
                ldm_x2(sb + 2 * (off + PART), bl[j][0], bl[j][1]);
            }
#pragma unroll
            for (int i = 0; i < 4; ++i)
#pragma unroll
                for (int j = 0; j < 4; ++j) {
                    mma16816(acc[i][j], ah[i], bh[j]);
                    mma16816(acc[i][j], ah[i], bl[j]);
                    mma16816(acc[i][j], al[i], bh[j]);
                }
        }
        __syncthreads();
    }

    // ---- epilogue: bias (+relu), write fp32 or hi/lo fp16 split ----
#pragma unroll
    for (int i = 0; i < 4; ++i) {
        const int r0 = m0 + wm * 64 + i * 16 + (lane >> 2);
#pragma unroll
        for (int j = 0; j < 4; ++j) {
            const int c0 = n0 + wn * 32 + j * 8 + (lane & 3) * 2;
            const float bz0 = __ldg(bias + c0), bz1 = __ldg(bias + c0 + 1);
            float v00 = acc[i][j][0] + bz0, v01 = acc[i][j][1] + bz1;
            float v10 = acc[i][j][2] + bz0, v11 = acc[i][j][3] + bz1;
            if (relu) {
                v00 = fmaxf(v00, 0.f); v01 = fmaxf(v01, 0.f);
                v10 = fmaxf(v10, 0.f); v11 = fmaxf(v11, 0.f);
            }
            if (Cf) {
                *(float2*)(Cf + (size_t)r0 * Nn + c0)       = make_float2(v00, v01);
                *(float2*)(Cf + (size_t)(r0 + 8) * Nn + c0) = make_float2(v10, v11);
            } else {
                __half h00 = __float2half_rn(v00), h01 = __float2half_rn(v01);
                __half h10 = __float2half_rn(v10), h11 = __float2half_rn(v11);
                __half2 hp0; hp0.x = h00; hp0.y = h01;
                __half2 hp1; hp1.x = h10; hp1.y = h11;
                __half2 lp0, lp1;
                lp0.x = __float2half_rn(v00 - __half2float(h00));
                lp0.y = __float2half_rn(v01 - __half2float(h01));
                lp1.x = __float2half_rn(v10 - __half2float(h10));
                lp1.y = __float2half_rn(v11 - __half2float(h11));
                *(__half2*)(Chi + (size_t)r0 * Nn + c0)       = hp0;
                *(__half2*)(Clo + (size_t)r0 * Nn + c0)       = lp0;
                *(__half2*)(Chi + (size_t)(r0 + 8) * Nn + c0) = hp1;
                *(__half2*)(Clo + (size_t)(r0 + 8) * Nn + c0) = lp1;
            }
        }
    }
}

// ---------------- pooling ----------------
__global__ void __launch_bounds__(128)
pool1(const int* __restrict__ lengths, const float* __restrict__ h2, float* __restrict__ partial) {
    const int b = blockIdx.x, y = blockIdx.y, h = threadIdx.x;
    const int valid = lengths[b] - 4;
    float s = 0.f;
    for (int w = y; w < valid; w += 8)
        s += h2[((size_t)b * Wn_ + w) * H2_ + h];
    partial[(b * 8 + y) * H2_ + h] = s;
}
__global__ void __launch_bounds__(128)
pool2(const int* __restrict__ lengths, const float* __restrict__ partial, float* __restrict__ out) {
    const int b = blockIdx.x, h = threadIdx.x;
    const int valid = lengths[b] - 4;
    float s = 0.f;
#pragma unroll
    for (int y = 0; y < 8; ++y) s += partial[(b * 8 + y) * H2_ + h];
    out[b * H2_ + h] = s / (float)valid;
}

// ---------------- launch ----------------
extern "C" void kernel_launch(void* const* d_in, const int* in_sizes, int n_in,
                              void* d_out, int out_size)
{
    const int*   x       = (const int*)  d_in[0];
    const int*   lengths = (const int*)  d_in[1];
    const float* table   = (const float*)d_in[2];
    const float* Wsl     = (const float*)d_in[3];
    const float* bsl     = (const float*)d_in[4];
    const float* W1      = (const float*)d_in[5];
    const float* b1      = (const float*)d_in[6];
    const float* W2      = (const float*)d_in[7];
    const float* b2      = (const float*)d_in[8];
    float*       out     = (float*)d_out;

    __half *embhi, *emblo, *w0hi, *w0lo, *w1hi, *w1lo, *w2hi, *w2lo;
    __half *h0hi, *h0lo, *h1hi, *h1lo;
    float *h2p, *poolp;
    cudaGetSymbolAddress((void**)&embhi, g_emb_hi);
    cudaGetSymbolAddress((void**)&emblo, g_emb_lo);
    cudaGetSymbolAddress((void**)&w0hi, g_w0hi);
    cudaGetSymbolAddress((void**)&w0lo, g_w0lo);
    cudaGetSymbolAddress((void**)&w1hi, g_w1hi);
    cudaGetSymbolAddress((void**)&w1lo, g_w1lo);
    cudaGetSymbolAddress((void**)&w2hi, g_w2hi);
    cudaGetSymbolAddress((void**)&w2lo, g_w2lo);
    cudaGetSymbolAddress((void**)&h0hi, g_h0hi);
    cudaGetSymbolAddress((void**)&h0lo, g_h0lo);
    cudaGetSymbolAddress((void**)&h1hi, g_h1hi);
    cudaGetSymbolAddress((void**)&h1lo, g_h1lo);
    cudaGetSymbolAddress((void**)&h2p, g_h2);
    cudaGetSymbolAddress((void**)&poolp, g_pool);

    const int SMEM = 3 * (4 * 128 * 40) * 2;   // 122880 B
    cudaFuncSetAttribute(gemm_hmma<true>,  cudaFuncAttributeMaxDynamicSharedMemorySize, SMEM);
    cudaFuncSetAttribute(gemm_hmma<false>, cudaFuncAttributeMaxDynamicSharedMemorySize, SMEM);

    // prep: gathered embedding hi/lo split + transposed weight hi/lo splits
    {
        int total = (B_ * S_ + 8) * E_;
        prep_emb<<<(total + 255) / 256, 256>>>(x, table);
    }
    prep_w<<<(H0_ * K0P + 255) / 256, 256>>>(Wsl, w0hi, w0lo, 1500, K0P, H0_);
    prep_w<<<(H1_ * H0_ + 255) / 256, 256>>>(W1, w1hi, w1lo, H0_, H0_, H1_);
    prep_w<<<(H2_ * H1_ + 255) / 256, 256>>>(W2, w2hi, w2lo, H1_, H1_, H2_);

    // layer 0: [65280 x 1536] (window view) x [1536 x 512]
    gemm_hmma<true><<<dim3(M_ / 128, H0_ / 128), 256, SMEM>>>(
        embhi, emblo, w0hi, w0lo, bsl, h0hi, h0lo, nullptr, K0P, H0_, 0);
    // layer 1: relu([65280 x 512] x [512 x 256])
    gemm_hmma<false><<<dim3(M_ / 128, H1_ / 128), 256, SMEM>>>(
        h0hi, h0lo, w1hi, w1lo, b1, h1hi, h1lo, nullptr, H0_, H1_, 1);
    // layer 2: relu([65280 x 256] x [256 x 128]) -> fp32
    gemm_hmma<false><<<dim3(M_ / 128, H2_ / 128), 256, SMEM>>>(
        h1hi, h1lo, w2hi, w2lo, b2, nullptr, nullptr, h2p, H1_, H2_, 1);

    // ragged mean pool
    pool1<<<dim3(B_, 8), 128>>>(lengths, h2p, poolp);
    pool2<<<B_, 128>>>(lengths, poolp, out);
}

// round 4
// speedup vs baseline: 3.7826x; 1.5580x over previous
#include <cuda_runtime.h>
#include <cuda_fp16.h>
#include <cstdint>
#include <cstddef>

// ---------------- problem constants ----------------
#define B_   64
#define S_   1024
#define E_   300
#define Wn_  1020
#define H0_  512
#define H1_  256
#define H2_  128
#define M_   (B_*Wn_)      // 65280
#define K0P  1536          // layer-0 K (1500) padded to 64

// ---------------- scratch (device globals) ----------------
__device__ __half g_emb[(size_t)(B_*S_+8)*E_];
__device__ __half g_w0hi[H0_*K0P], g_w0lo[H0_*K0P];
__device__ __half g_w1hi[H1_*H0_], g_w1lo[H1_*H0_];
__device__ __half g_w2hi[H2_*H1_], g_w2lo[H2_*H1_];
__device__ __half g_h0[(size_t)M_*H0_];
__device__ __half g_h1[(size_t)M_*H1_];
__device__ float g_h2[(size_t)M_*H2_];
__device__ float g_pool[B_*8*H2_];

// ---------------- asm helpers (plain sm_80+ features only) ----------------
__device__ __forceinline__ uint32_t smem_u32(const void* p) {
    uint32_t a;
    asm("{ .reg .u64 t; cvta.to.shared.u64 t, %1; cvt.u32.u64 %0, t; }" : "=r"(a) : "l"(p));
    return a;
}
__device__ __forceinline__ void cpa8(uint32_t s, const void* g) {
    asm volatile("cp.async.ca.shared.global [%0], [%1], 8;" :: "r"(s), "l"(g));
}
__device__ __forceinline__ void cpa16(uint32_t s, const void* g) {
    asm volatile("cp.async.cg.shared.global [%0], [%1], 16;" :: "r"(s), "l"(g));
}
__device__ __forceinline__ void cp_commit() { asm volatile("cp.async.commit_group;"); }
template<int N> __device__ __forceinline__ void cp_wait() {
    asm volatile("cp.async.wait_group %0;" :: "n"(N));
}
__device__ __forceinline__ void ldm_x4(uint32_t a, uint32_t& r0, uint32_t& r1, uint32_t& r2, uint32_t& r3) {
    asm volatile("ldmatrix.sync.aligned.m8n8.x4.shared.b16 {%0,%1,%2,%3}, [%4];"
                 : "=r"(r0), "=r"(r1), "=r"(r2), "=r"(r3) : "r"(a));
}
__device__ __forceinline__ void ldm_x2(uint32_t a, uint32_t& r0, uint32_t& r1) {
    asm volatile("ldmatrix.sync.aligned.m8n8.x2.shared.b16 {%0,%1}, [%2];"
                 : "=r"(r0), "=r"(r1) : "r"(a));
}
__device__ __forceinline__ void mma16816(float* c, const uint32_t* a, const uint32_t* b) {
    asm volatile("mma.sync.aligned.m16n8k16.row.col.f32.f16.f16.f32 "
                 "{%0,%1,%2,%3}, {%4,%5,%6,%7}, {%8,%9}, {%0,%1,%2,%3};"
                 : "+f"(c[0]), "+f"(c[1]), "+f"(c[2]), "+f"(c[3])
                 : "r"(a[0]), "r"(a[1]), "r"(a[2]), "r"(a[3]), "r"(b[0]), "r"(b[1]));
}

// ---------------- prep kernels ----------------
__global__ void prep_emb(const int* __restrict__ x, const float* __restrict__ table) {
    int idx = blockIdx.x * 256 + threadIdx.x;
    const int total = (B_ * S_ + 8) * E_;
    if (idx >= total) return;
    int row = idx / E_;
    int e = idx - row * E_;
    float v = 0.f;
    if (row < B_ * S_) {
        int tok = x[row];
        v = table[(size_t)tok * E_ + e];
    }
    g_emb[idx] = __float2half_rn(v);
}

__global__ void prep_w(const float* __restrict__ W, __half* __restrict__ Thi,
                       __half* __restrict__ Tlo, int K, int Kpad, int Nn) {
    int idx = blockIdx.x * 256 + threadIdx.x;
    if (idx >= Nn * Kpad) return;
    int n = idx / Kpad;
    int k = idx - n * Kpad;
    float v = (k < K) ? W[(size_t)k * Nn + n] : 0.f;   // transpose to [n][k]
    __half hi = __float2half_rn(v);
    __half lo = __float2half_rn(v - __half2float(hi));
    Thi[idx] = hi; Tlo[idx] = lo;
}

// ---------------- HMMA split-weight GEMM ----------------
// CTA 128x128, warps 2(m) x 4(n), warp tile 64x32, BK=32, 3 cp.async stages.
// C = act( A @ (Wh + Wl)^T + bias ): 2 MMAs per tile (A*Wh + A*Wl).
// A: single fp16, row-major [m][K] or sliding-window view into emb.
// W: transposed [n][Kpad], hi/lo split.
template<bool WIN>
__global__ void __launch_bounds__(256, 2)
gemm_hmma(const __half* __restrict__ Ag,
          const __half* __restrict__ Bhg, const __half* __restrict__ Blg,
          const float* __restrict__ bias,
          __half* __restrict__ Ch, float* __restrict__ Cf,
          int K, int Nn, int relu)
{
    constexpr int RS   = 40;            // smem row stride (halfs): ldmatrix conflict-free
    constexpr int PART = 128 * RS;      // one operand part (halfs)
    constexpr int STG  = 3 * PART;      // A, Bh, Bl
    constexpr int NCA  = WIN ? 4 : 2;   // A chunks per thread

    extern __shared__ __half sm[];
    const uint32_t smb = smem_u32(sm);

    const int tid  = threadIdx.x;
    const int lane = tid & 31;
    const int wid  = tid >> 5;
    const int wm   = wid & 1;
    const int wn   = wid >> 1;
    const int m0   = blockIdx.x * 128;
    const int n0   = blockIdx.y * 128;
    const int niter = K >> 5;

    // ---- A load descriptors (1 part) ----
    const __half* aptr[NCA];
    uint32_t asmoff[NCA];
    {
        const int CS  = WIN ? 4 : 8;    // chunk size halfs (8B / 16B)
        const int CPR = 32 / CS;        // chunks per 32-half row
#pragma unroll
        for (int t = 0; t < NCA; ++t) {
            int idx  = tid + t * 256;   // 0 .. 128*CPR-1
            int row  = idx / CPR;
            int c    = idx - row * CPR;
            size_t rb;
            if (WIN) {
                int m = m0 + row;
                int b = m / Wn_;
                int w = m - b * Wn_;
                rb = (size_t)(b * S_ + w) * E_;
            } else {
                rb = (size_t)(m0 + row) * K;
            }
            aptr[t]   = Ag + rb + c * CS;
            asmoff[t] = row * RS + c * CS;
        }
    }
    // ---- B load descriptors (2 parts, 16B chunks): 2*128*4 = 1024 -> 4/thread
    const __half* bptr[4];
    uint32_t bsmoff[4];
#pragma unroll
    for (int t = 0; t < 4; ++t) {
        int idx  = tid + t * 256;
        int part = idx >> 9;            // 0..1
        int rem  = idx & 511;
        int row  = rem >> 2;
        int c    = rem & 3;
        bptr[t]   = (part ? Blg : Bhg) + (size_t)(n0 + row) * K + c * 8;
        bsmoff[t] = PART + part * PART + row * RS + c * 8;
    }

    auto load_stage = [&](int stage, int k0) {
        uint32_t sb = smb + 2 * (uint32_t)(stage * STG);
#pragma unroll
        for (int t = 0; t < NCA; ++t) {
            if (WIN) cpa8(sb + 2 * asmoff[t], aptr[t] + k0);
            else     cpa16(sb + 2 * asmoff[t], aptr[t] + k0);
        }
#pragma unroll
        for (int t = 0; t < 4; ++t)
            cpa16(sb + 2 * bsmoff[t], bptr[t] + k0);
        cp_commit();
    };

    const uint32_t a_row = wm * 64 + (lane & 15);
    const uint32_t a_col = (lane >> 4) * 8;
    const uint32_t b_row = wn * 32 + (lane & 7);
    const uint32_t b_col = ((lane >> 3) & 1) * 8;

    float acc[4][4][4];
#pragma unroll
    for (int i = 0; i < 4; ++i)
#pragma unroll
        for (int j = 0; j < 4; ++j)
#pragma unroll
            for (int q = 0; q < 4; ++q) acc[i][j][q] = 0.f;

    load_stage(0, 0);
    load_stage(1, 32);

    for (int it = 0; it < niter; ++it) {
        if (it + 1 < niter) cp_wait<1>(); else cp_wait<0>();
        __syncthreads();
        if (it + 2 < niter) load_stage((it + 2) % 3, (it + 2) * 32);

        const uint32_t sb = smb + 2 * (uint32_t)((it % 3) * STG);
#pragma unroll
        for (int ks = 0; ks < 2; ++ks) {
            uint32_t af[4][4], bh[4][2], bl[4][2];
#pragma unroll
            for (int i = 0; i < 4; ++i) {
                uint32_t off = (a_row + i * 16) * RS + (ks * 16 + a_col);
                ldm_x4(sb + 2 * off, af[i][0], af[i][1], af[i][2], af[i][3]);
            }
#pragma unroll
            for (int j = 0; j < 4; ++j) {
                uint32_t off = PART + (b_row + j * 8) * RS + (ks * 16 + b_col);
                ldm_x2(sb + 2 * off,          bh[j][0], bh[j][1]);
                ldm_x2(sb + 2 * (off + PART), bl[j][0], bl[j][1]);
            }
#pragma unroll
            for (int i = 0; i < 4; ++i)
#pragma unroll
                for (int j = 0; j < 4; ++j) {
                    mma16816(acc[i][j], af[i], bh[j]);
                    mma16816(acc[i][j], af[i], bl[j]);
                }
        }
        __syncthreads();
    }

    // ---- epilogue: bias (+relu), write fp16 (rounded) or fp32 ----
#pragma unroll
    for (int i = 0; i < 4; ++i) {
        const int r0 = m0 + wm * 64 + i * 16 + (lane >> 2);
#pragma unroll
        for (int j = 0; j < 4; ++j) {
            const int c0 = n0 + wn * 32 + j * 8 + (lane & 3) * 2;
            const float bz0 = __ldg(bias + c0), bz1 = __ldg(bias + c0 + 1);
            float v00 = acc[i][j][0] + bz0, v01 = acc[i][j][1] + bz1;
            float v10 = acc[i][j][2] + bz0, v11 = acc[i][j][3] + bz1;
            if (relu) {
                v00 = fmaxf(v00, 0.f); v01 = fmaxf(v01, 0.f);
                v10 = fmaxf(v10, 0.f); v11 = fmaxf(v11, 0.f);
            }
            if (Cf) {
                *(float2*)(Cf + (size_t)r0 * Nn + c0)       = make_float2(v00, v01);
                *(float2*)(Cf + (size_t)(r0 + 8) * Nn + c0) = make_float2(v10, v11);
            } else {
                __half2 hp0, hp1;
                hp0.x = __float2half_rn(v00); hp0.y = __float2half_rn(v01);
                hp1.x = __float2half_rn(v10); hp1.y = __float2half_rn(v11);
                *(__half2*)(Ch + (size_t)r0 * Nn + c0)       = hp0;
                *(__half2*)(Ch + (size_t)(r0 + 8) * Nn + c0) = hp1;
            }
        }
    }
}

// ---------------- pooling ----------------
__global__ void __launch_bounds__(128)
pool1(const int* __restrict__ lengths, const float* __restrict__ h2, float* __restrict__ partial) {
    const int b = blockIdx.x, y = blockIdx.y, h = threadIdx.x;
    const int valid = lengths[b] - 4;
    float s = 0.f;
    for (int w = y; w < valid; w += 8)
        s += h2[((size_t)b * Wn_ + w) * H2_ + h];
    partial[(b * 8 + y) * H2_ + h] = s;
}
__global__ void __launch_bounds__(128)
pool2(const int* __restrict__ lengths, const float* __restrict__ partial, float* __restrict__ out) {
    const int b = blockIdx.x, h = threadIdx.x;
    const int valid = lengths[b] - 4;
    float s = 0.f;
#pragma unroll
    for (int y = 0; y < 8; ++y) s += partial[(b * 8 + y) * H2_ + h];
    out[b * H2_ + h] = s / (float)valid;
}

// ---------------- launch ----------------
extern "C" void kernel_launch(void* const* d_in, const int* in_sizes, int n_in,
                              void* d_out, int out_size)
{
    const int*   x       = (const int*)  d_in[0];
    const int*   lengths = (const int*)  d_in[1];
    const float* table   = (const float*)d_in[2];
    const float* Wsl     = (const float*)d_in[3];
    const float* bsl     = (const float*)d_in[4];
    const float* W1      = (const float*)d_in[5];
    const float* b1      = (const float*)d_in[6];
    const float* W2      = (const float*)d_in[7];
    const float* b2      = (const float*)d_in[8];
    float*       out     = (float*)d_out;

    __half *embp, *w0hi, *w0lo, *w1hi, *w1lo, *w2hi, *w2lo, *h0p, *h1p;
    float *h2p, *poolp;
    cudaGetSymbolAddress((void**)&embp, g_emb);
    cudaGetSymbolAddress((void**)&w0hi, g_w0hi);
    cudaGetSymbolAddress((void**)&w0lo, g_w0lo);
    cudaGetSymbolAddress((void**)&w1hi, g_w1hi);
    cudaGetSymbolAddress((void**)&w1lo, g_w1lo);
    cudaGetSymbolAddress((void**)&w2hi, g_w2hi);
    cudaGetSymbolAddress((void**)&w2lo, g_w2lo);
    cudaGetSymbolAddress((void**)&h0p, g_h0);
    cudaGetSymbolAddress((void**)&h1p, g_h1);
    cudaGetSymbolAddress((void**)&h2p, g_h2);
    cudaGetSymbolAddress((void**)&poolp, g_pool);

    const int SMEM = 3 * (3 * 128 * 40) * 2;   // 92160 B per CTA, 2 CTAs/SM
    cudaFuncSetAttribute(gemm_hmma<true>,  cudaFuncAttributeMaxDynamicSharedMemorySize, SMEM);
    cudaFuncSetAttribute(gemm_hmma<false>, cudaFuncAttributeMaxDynamicSharedMemorySize, SMEM);

    // prep: gathered embedding (rounded fp16) + transposed weight hi/lo splits
    {
        int total = (B_ * S_ + 8) * E_;
        prep_emb<<<(total + 255) / 256, 256>>>(x, table);
    }
    prep_w<<<(H0_ * K0P + 255) / 256, 256>>>(Wsl, w0hi, w0lo, 1500, K0P, H0_);
    prep_w<<<(H1_ * H0_ + 255) / 256, 256>>>(W1, w1hi, w1lo, H0_, H0_, H1_);
    prep_w<<<(H2_ * H1_ + 255) / 256, 256>>>(W2, w2hi, w2lo, H1_, H1_, H2_);

    // layer 0: [65280 x 1536] (window view) x [1536 x 512]
    gemm_hmma<true><<<dim3(M_ / 128, H0_ / 128), 256, SMEM>>>(
        embp, w0hi, w0lo, bsl, h0p, nullptr, K0P, H0_, 0);
    // layer 1: relu([65280 x 512] x [512 x 256])
    gemm_hmma<false><<<dim3(M_ / 128, H1_ / 128), 256, SMEM>>>(
        h0p, w1hi, w1lo, b1, h1p, nullptr, H0_, H1_, 1);
    // layer 2: relu([65280 x 256] x [256 x 128]) -> fp32
    gemm_hmma<false><<<dim3(M_ / 128, H2_ / 128), 256, SMEM>>>(
        h1p, w2hi, w2lo, b2, nullptr, h2p, H1_, H2_, 1);

    // ragged mean pool
    pool1<<<dim3(B_, 8), 128>>>(lengths, h2p, poolp);
    pool2<<<B_, 128>>>(lengths, poolp, out);
}

// round 5
// speedup vs baseline: 5.6952x; 1.5056x over previous
#include <cuda_runtime.h>
#include <cuda_fp16.h>
#include <cstdint>
#include <cstddef>

// ---------------- problem constants ----------------
#define B_   64
#define S_   1024
#define E_   300
#define Wn_  1020
#define H0_  512
#define H1_  256
#define H2_  128
#define M_   (B_*Wn_)      // 65280
#define K0P  1536          // layer-0 K (1500) padded to 64

// ---------------- scratch (device globals) ----------------
__device__ __half g_emb[(size_t)(B_*S_+8)*E_];
__device__ __half g_w0[H0_*K0P];
__device__ __half g_w1[H1_*H0_];
__device__ __half g_w2[H2_*H1_];
__device__ __half g_h0[(size_t)M_*H0_];
__device__ __half g_h1[(size_t)M_*H1_];
__device__ float g_h2[(size_t)M_*H2_];
__device__ float g_pool[B_*8*H2_];

// ---------------- asm helpers (plain sm_80+ features only) ----------------
__device__ __forceinline__ uint32_t smem_u32(const void* p) {
    uint32_t a;
    asm("{ .reg .u64 t; cvta.to.shared.u64 t, %1; cvt.u32.u64 %0, t; }" : "=r"(a) : "l"(p));
    return a;
}
__device__ __forceinline__ void cpa8(uint32_t s, const void* g) {
    asm volatile("cp.async.ca.shared.global [%0], [%1], 8;" :: "r"(s), "l"(g));
}
__device__ __forceinline__ void cpa16(uint32_t s, const void* g) {
    asm volatile("cp.async.cg.shared.global [%0], [%1], 16;" :: "r"(s), "l"(g));
}
__device__ __forceinline__ void cp_commit() { asm volatile("cp.async.commit_group;"); }
template<int N> __device__ __forceinline__ void cp_wait() {
    asm volatile("cp.async.wait_group %0;" :: "n"(N));
}
__device__ __forceinline__ void ldm_x4(uint32_t a, uint32_t& r0, uint32_t& r1, uint32_t& r2, uint32_t& r3) {
    asm volatile("ldmatrix.sync.aligned.m8n8.x4.shared.b16 {%0,%1,%2,%3}, [%4];"
                 : "=r"(r0), "=r"(r1), "=r"(r2), "=r"(r3) : "r"(a));
}
__device__ __forceinline__ void ldm_x2(uint32_t a, uint32_t& r0, uint32_t& r1) {
    asm volatile("ldmatrix.sync.aligned.m8n8.x2.shared.b16 {%0,%1}, [%2];"
                 : "=r"(r0), "=r"(r1) : "r"(a));
}
__device__ __forceinline__ void mma16816(float* c, const uint32_t* a, const uint32_t* b) {
    asm volatile("mma.sync.aligned.m16n8k16.row.col.f32.f16.f16.f32 "
                 "{%0,%1,%2,%3}, {%4,%5,%6,%7}, {%8,%9}, {%0,%1,%2,%3};"
                 : "+f"(c[0]), "+f"(c[1]), "+f"(c[2]), "+f"(c[3])
                 : "r"(a[0]), "r"(a[1]), "r"(a[2]), "r"(a[3]), "r"(b[0]), "r"(b[1]));
}

// ---------------- prep kernels ----------------
__global__ void prep_emb(const int* __restrict__ x, const float* __restrict__ table) {
    int idx = blockIdx.x * 256 + threadIdx.x;
    const int total = (B_ * S_ + 8) * E_;
    if (idx >= total) return;
    int row = idx / E_;
    int e = idx - row * E_;
    float v = 0.f;
    if (row < B_ * S_) {
        int tok = x[row];
        v = table[(size_t)tok * E_ + e];
    }
    g_emb[idx] = __float2half_rn(v);
}

__global__ void prep_w(const float* __restrict__ W, __half* __restrict__ T,
                       int K, int Kpad, int Nn) {
    int idx = blockIdx.x * 256 + threadIdx.x;
    if (idx >= Nn * Kpad) return;
    int n = idx / Kpad;
    int k = idx - n * Kpad;
    float v = (k < K) ? W[(size_t)k * Nn + n] : 0.f;   // transpose to [n][k]
    T[idx] = __float2half_rn(v);
}

// ---------------- HMMA fp16 GEMM ----------------
// CTA 128x128, warps 2(m) x 4(n), warp tile 64x32, BK=32, 3 cp.async stages.
// C = act( A @ W^T + bias ): 1 MMA per tile.
// A: fp16 row-major [m][K] or sliding-window view into emb. W: transposed [n][Kpad].
template<bool WIN>
__global__ void __launch_bounds__(256, 2)
gemm_hmma(const __half* __restrict__ Ag, const __half* __restrict__ Bg,
          const float* __restrict__ bias,
          __half* __restrict__ Ch, float* __restrict__ Cf,
          int K, int Nn, int relu)
{
    constexpr int RS   = 40;            // smem row stride (halfs): ldmatrix conflict-free
    constexpr int PART = 128 * RS;      // one operand (halfs)
    constexpr int STG  = 2 * PART;      // A, B
    constexpr int NCA  = WIN ? 4 : 2;   // A chunks per thread

    extern __shared__ __half sm[];
    const uint32_t smb = smem_u32(sm);

    const int tid  = threadIdx.x;
    const int lane = tid & 31;
    const int wid  = tid >> 5;
    const int wm   = wid & 1;
    const int wn   = wid >> 1;
    const int m0   = blockIdx.x * 128;
    const int n0   = blockIdx.y * 128;
    const int niter = K >> 5;

    // ---- A load descriptors ----
    const __half* aptr[NCA];
    uint32_t asmoff[NCA];
    {
        const int CS  = WIN ? 4 : 8;    // chunk size halfs (8B / 16B)
        const int CPR = 32 / CS;
#pragma unroll
        for (int t = 0; t < NCA; ++t) {
            int idx  = tid + t * 256;
            int row  = idx / CPR;
            int c    = idx - row * CPR;
            size_t rb;
            if (WIN) {
                int m = m0 + row;
                int b = m / Wn_;
                int w = m - b * Wn_;
                rb = (size_t)(b * S_ + w) * E_;
            } else {
                rb = (size_t)(m0 + row) * K;
            }
            aptr[t]   = Ag + rb + c * CS;
            asmoff[t] = row * RS + c * CS;
        }
    }
    // ---- B load descriptors: 128 rows x 4 chunks = 512 -> 2/thread ----
    const __half* bptr[2];
    uint32_t bsmoff[2];
#pragma unroll
    for (int t = 0; t < 2; ++t) {
        int idx  = tid + t * 256;
        int row  = idx >> 2;
        int c    = idx & 3;
        bptr[t]   = Bg + (size_t)(n0 + row) * K + c * 8;
        bsmoff[t] = PART + row * RS + c * 8;
    }

    auto load_stage = [&](int stage, int k0) {
        uint32_t sb = smb + 2 * (uint32_t)(stage * STG);
#pragma unroll
        for (int t = 0; t < NCA; ++t) {
            if (WIN) cpa8(sb + 2 * asmoff[t], aptr[t] + k0);
            else     cpa16(sb + 2 * asmoff[t], aptr[t] + k0);
        }
#pragma unroll
        for (int t = 0; t < 2; ++t)
            cpa16(sb + 2 * bsmoff[t], bptr[t] + k0);
        cp_commit();
    };

    const uint32_t a_row = wm * 64 + (lane & 15);
    const uint32_t a_col = (lane >> 4) * 8;
    const uint32_t b_row = wn * 32 + (lane & 7);
    const uint32_t b_col = ((lane >> 3) & 1) * 8;

    float acc[4][4][4];
#pragma unroll
    for (int i = 0; i < 4; ++i)
#pragma unroll
        for (int j = 0; j < 4; ++j)
#pragma unroll
            for (int q = 0; q < 4; ++q) acc[i][j][q] = 0.f;

    load_stage(0, 0);
    load_stage(1, 32);

    for (int it = 0; it < niter; ++it) {
        if (it + 1 < niter) cp_wait<1>(); else cp_wait<0>();
        __syncthreads();
        if (it + 2 < niter) load_stage((it + 2) % 3, (it + 2) * 32);

        const uint32_t sb = smb + 2 * (uint32_t)((it % 3) * STG);
#pragma unroll
        for (int ks = 0; ks < 2; ++ks) {
            uint32_t af[4][4], bf[4][2];
#pragma unroll
            for (int i = 0; i < 4; ++i) {
                uint32_t off = (a_row + i * 16) * RS + (ks * 16 + a_col);
                ldm_x4(sb + 2 * off, af[i][0], af[i][1], af[i][2], af[i][3]);
            }
#pragma unroll
            for (int j = 0; j < 4; ++j) {
                uint32_t off = PART + (b_row + j * 8) * RS + (ks * 16 + b_col);
                ldm_x2(sb + 2 * off, bf[j][0], bf[j][1]);
            }
#pragma unroll
            for (int i = 0; i < 4; ++i)
#pragma unroll
                for (int j = 0; j < 4; ++j)
                    mma16816(acc[i][j], af[i], bf[j]);
        }
        __syncthreads();
    }

    // ---- epilogue: bias (+relu), write fp16 or fp32 ----
#pragma unroll
    for (int i = 0; i < 4; ++i) {
        const int r0 = m0 + wm * 64 + i * 16 + (lane >> 2);
#pragma unroll
        for (int j = 0; j < 4; ++j) {
            const int c0 = n0 + wn * 32 + j * 8 + (lane & 3) * 2;
            const float bz0 = __ldg(bias + c0), bz1 = __ldg(bias + c0 + 1);
            float v00 = acc[i][j][0] + bz0, v01 = acc[i][j][1] + bz1;
            float v10 = acc[i][j][2] + bz0, v11 = acc[i][j][3] + bz1;
            if (relu) {
                v00 = fmaxf(v00, 0.f); v01 = fmaxf(v01, 0.f);
                v10 = fmaxf(v10, 0.f); v11 = fmaxf(v11, 0.f);
            }
            if (Cf) {
                *(float2*)(Cf + (size_t)r0 * Nn + c0)       = make_float2(v00, v01);
                *(float2*)(Cf + (size_t)(r0 + 8) * Nn + c0) = make_float2(v10, v11);
            } else {
                __half2 hp0, hp1;
                hp0.x = __float2half_rn(v00); hp0.y = __float2half_rn(v01);
                hp1.x = __float2half_rn(v10); hp1.y = __float2half_rn(v11);
                *(__half2*)(Ch + (size_t)r0 * Nn + c0)       = hp0;
                *(__half2*)(Ch + (size_t)(r0 + 8) * Nn + c0) = hp1;
            }
        }
    }
}

// ---------------- pooling ----------------
__global__ void __launch_bounds__(128)
pool1(const int* __restrict__ lengths, const float* __restrict__ h2, float* __restrict__ partial) {
    const int b = blockIdx.x, y = blockIdx.y, h = threadIdx.x;
    const int valid = lengths[b] - 4;
    float s = 0.f;
    for (int w = y; w < valid; w += 8)
        s += h2[((size_t)b * Wn_ + w) * H2_ + h];
    partial[(b * 8 + y) * H2_ + h] = s;
}
__global__ void __launch_bounds__(128)
pool2(const int* __restrict__ lengths, const float* __restrict__ partial, float* __restrict__ out) {
    const int b = blockIdx.x, h = threadIdx.x;
    const int valid = lengths[b] - 4;
    float s = 0.f;
#pragma unroll
    for (int y = 0; y < 8; ++y) s += partial[(b * 8 + y) * H2_ + h];
    out[b * H2_ + h] = s / (float)valid;
}

// ---------------- launch ----------------
extern "C" void kernel_launch(void* const* d_in, const int* in_sizes, int n_in,
                              void* d_out, int out_size)
{
    const int*   x       = (const int*)  d_in[0];
    const int*   lengths = (const int*)  d_in[1];
    const float* table   = (const float*)d_in[2];
    const float* Wsl     = (const float*)d_in[3];
    const float* bsl     = (const float*)d_in[4];
    const float* W1      = (const float*)d_in[5];
    const float* b1      = (const float*)d_in[6];
    const float* W2      = (const float*)d_in[7];
    const float* b2      = (const float*)d_in[8];
    float*       out     = (float*)d_out;

    __half *embp, *w0p, *w1p, *w2p, *h0p, *h1p;
    float *h2p, *poolp;
    cudaGetSymbolAddress((void**)&embp, g_emb);
    cudaGetSymbolAddress((void**)&w0p, g_w0);
    cudaGetSymbolAddress((void**)&w1p, g_w1);
    cudaGetSymbolAddress((void**)&w2p, g_w2);
    cudaGetSymbolAddress((void**)&h0p, g_h0);
    cudaGetSymbolAddress((void**)&h1p, g_h1);
    cudaGetSymbolAddress((void**)&h2p, g_h2);
    cudaGetSymbolAddress((void**)&poolp, g_pool);

    const int SMEM = 3 * (2 * 128 * 40) * 2;   // 61440 B per CTA, 2 CTAs/SM
    cudaFuncSetAttribute(gemm_hmma<true>,  cudaFuncAttributeMaxDynamicSharedMemorySize, SMEM);
    cudaFuncSetAttribute(gemm_hmma<false>, cudaFuncAttributeMaxDynamicSharedMemorySize, SMEM);

    // prep: gathered fp16 embedding + transposed fp16 weights
    {
        int total = (B_ * S_ + 8) * E_;
        prep_emb<<<(total + 255) / 256, 256>>>(x, table);
    }
    prep_w<<<(H0_ * K0P + 255) / 256, 256>>>(Wsl, w0p, 1500, K0P, H0_);
    prep_w<<<(H1_ * H0_ + 255) / 256, 256>>>(W1, w1p, H0_, H0_, H1_);
    prep_w<<<(H2_ * H1_ + 255) / 256, 256>>>(W2, w2p, H1_, H1_, H2_);

    // layer 0: [65280 x 1536] (window view) x [1536 x 512]
    gemm_hmma<true><<<dim3(M_ / 128, H0_ / 128), 256, SMEM>>>(
        embp, w0p, bsl, h0p, nullptr, K0P, H0_, 0);
    // layer 1: relu([65280 x 512] x [512 x 256])
    gemm_hmma<false><<<dim3(M_ / 128, H1_ / 128), 256, SMEM>>>(
        h0p, w1p, b1, h1p, nullptr, H0_, H1_, 1);
    // layer 2: relu([65280 x 256] x [256 x 128]) -> fp32
    gemm_hmma<false><<<dim3(M_ / 128, H2_ / 128), 256, SMEM>>>(
        h1p, w2p, b2, nullptr, h2p, H1_, H2_, 1);

    // ragged mean pool
    pool1<<<dim3(B_, 8), 128>>>(lengths, h2p, poolp);
    pool2<<<B_, 128>>>(lengths, poolp, out);
}

// round 6
// speedup vs baseline: 6.3954x; 1.1229x over previous
#include <cuda_runtime.h>
#include <cuda_fp16.h>
#include <cstdint>
#include <cstddef>

// ---------------- problem constants ----------------
#define B_   64
#define S_   1024
#define E_   300
#define Wn_  1020
#define H0_  512
#define H1_  256
#define H2_  128
#define M_   (B_*Wn_)      // 65280
#define K0P  1536          // layer-0 K (1500) padded to 64

// ---------------- scratch (device globals) ----------------
__device__ __half g_emb[(size_t)(B_*S_+8)*E_];
__device__ __half g_w0[H0_*K0P];
__device__ __half g_w1[H1_*H0_];
__device__ __half g_w2[H2_*H1_];
__device__ __half g_h0[(size_t)M_*H0_];
__device__ __half g_h1[(size_t)M_*H1_];
__device__ float g_pool[B_*H2_];

// ---------------- asm helpers (plain sm_80+ features only) ----------------
__device__ __forceinline__ uint32_t smem_u32(const void* p) {
    uint32_t a;
    asm("{ .reg .u64 t; cvta.to.shared.u64 t, %1; cvt.u32.u64 %0, t; }" : "=r"(a) : "l"(p));
    return a;
}
__device__ __forceinline__ void cpa8(uint32_t s, const void* g) {
    asm volatile("cp.async.ca.shared.global [%0], [%1], 8;" :: "r"(s), "l"(g));
}
__device__ __forceinline__ void cpa16(uint32_t s, const void* g) {
    asm volatile("cp.async.cg.shared.global [%0], [%1], 16;" :: "r"(s), "l"(g));
}
__device__ __forceinline__ void cp_commit() { asm volatile("cp.async.commit_group;"); }
template<int N> __device__ __forceinline__ void cp_wait() {
    asm volatile("cp.async.wait_group %0;" :: "n"(N));
}
__device__ __forceinline__ void ldm_x4(uint32_t a, uint32_t& r0, uint32_t& r1, uint32_t& r2, uint32_t& r3) {
    asm volatile("ldmatrix.sync.aligned.m8n8.x4.shared.b16 {%0,%1,%2,%3}, [%4];"
                 : "=r"(r0), "=r"(r1), "=r"(r2), "=r"(r3) : "r"(a));
}
__device__ __forceinline__ void mma16816(float* c, const uint32_t* a, const uint32_t* b) {
    asm volatile("mma.sync.aligned.m16n8k16.row.col.f32.f16.f16.f32 "
                 "{%0,%1,%2,%3}, {%4,%5,%6,%7}, {%8,%9}, {%0,%1,%2,%3};"
                 : "+f"(c[0]), "+f"(c[1]), "+f"(c[2]), "+f"(c[3])
                 : "r"(a[0]), "r"(a[1]), "r"(a[2]), "r"(a[3]), "r"(b[0]), "r"(b[1]));
}

// ---------------- prep kernels ----------------
__global__ void prep_emb(const int* __restrict__ x, const float* __restrict__ table) {
    int idx = blockIdx.x * 256 + threadIdx.x;
    const int total = (B_ * S_ + 8) * E_;
    if (idx >= total) return;
    int row = idx / E_;
    int e = idx - row * E_;
    float v = 0.f;
    if (row < B_ * S_) {
        int tok = x[row];
        v = table[(size_t)tok * E_ + e];
    }
    g_emb[idx] = __float2half_rn(v);
}

__global__ void prep_w(const float* __restrict__ W, __half* __restrict__ T,
                       int K, int Kpad, int Nn) {
    int idx = blockIdx.x * 256 + threadIdx.x;
    if (idx >= Nn * Kpad) return;
    int n = idx / Kpad;
    int k = idx - n * Kpad;
    float v = (k < K) ? W[(size_t)k * Nn + n] : 0.f;   // transpose to [n][k]
    T[idx] = __float2half_rn(v);
}

__global__ void zero_pool() {
    int i = blockIdx.x * 256 + threadIdx.x;
    if (i < B_ * H2_) g_pool[i] = 0.f;
}

// ---------------- HMMA fp16 GEMM, 4 warps, warp tile 64x64 ----------------
// CTA 128x128, warps 2(m) x 2(n), BK=32, 3 cp.async stages, 1 sync/iter.
// C = act( A @ W^T + bias ). POOL: masked column-sum accumulation into g_pool.
template<bool WIN, bool POOL>
__global__ void __launch_bounds__(128, 2)
gemm_hmma(const __half* __restrict__ Ag, const __half* __restrict__ Bg,
          const float* __restrict__ bias, const int* __restrict__ lengths,
          __half* __restrict__ Ch,
          int K, int Nn, int relu)
{
    constexpr int RS   = 40;            // smem row stride (halfs)
    constexpr int PART = 128 * RS;
    constexpr int STG  = 2 * PART;
    constexpr int NCA  = WIN ? 8 : 4;   // A chunks per thread (8B / 16B)

    extern __shared__ __half sm[];
    __shared__ float sacc[2][128];
    const uint32_t smb = smem_u32(sm);

    const int tid  = threadIdx.x;
    const int lane = tid & 31;
    const int wid  = tid >> 5;
    const int wm   = wid & 1;           // 0..1 (M)
    const int wn   = wid >> 1;          // 0..1 (N)
    const int m0   = blockIdx.x * 128;
    const int n0   = blockIdx.y * 128;
    const int niter = K >> 5;

    if (POOL && tid < 128) { sacc[0][tid] = 0.f; sacc[1][tid] = 0.f; }

    // ---- A load descriptors ----
    const __half* aptr[NCA];
    uint32_t asmoff[NCA];
    {
        const int CS  = WIN ? 4 : 8;
        const int CPR = 32 / CS;
#pragma unroll
        for (int t = 0; t < NCA; ++t) {
            int idx  = tid + t * 128;
            int row  = idx / CPR;
            int c    = idx - row * CPR;
            size_t rb;
            if (WIN) {
                int m = m0 + row;
                int b = m / Wn_;
                int w = m - b * Wn_;
                rb = (size_t)(b * S_ + w) * E_;
            } else {
                rb = (size_t)(m0 + row) * K;
            }
            aptr[t]   = Ag + rb + c * CS;
            asmoff[t] = row * RS + c * CS;
        }
    }
    // ---- B load descriptors: 128 rows x 4 x16B = 512 -> 4/thread ----
    const __half* bptr[4];
    uint32_t bsmoff[4];
#pragma unroll
    for (int t = 0; t < 4; ++t) {
        int idx  = tid + t * 128;
        int row  = idx >> 2;
        int c    = idx & 3;
        bptr[t]   = Bg + (size_t)(n0 + row) * K + c * 8;
        bsmoff[t] = PART + row * RS + c * 8;
    }

    auto load_stage = [&](int stage, int k0) {
        uint32_t sb = smb + 2 * (uint32_t)(stage * STG);
#pragma unroll
        for (int t = 0; t < NCA; ++t) {
            if (WIN) cpa8(sb + 2 * asmoff[t], aptr[t] + k0);
            else     cpa16(sb + 2 * asmoff[t], aptr[t] + k0);
        }
#pragma unroll
        for (int t = 0; t < 4; ++t)
            cpa16(sb + 2 * bsmoff[t], bptr[t] + k0);
        cp_commit();
    };

    // fragment addressing
    const uint32_t a_row  = wm * 64 + (lane & 15);
    const uint32_t a_col  = (lane >> 4) * 8;
    // B paired-x4: lanes 0-7 -> (j=2jj, k0), 8-15 -> (j=2jj, k8),
    //              16-23 -> (j=2jj+1, k0), 24-31 -> (j=2jj+1, k8)
    const uint32_t b_row2 = wn * 64 + (lane & 7) + ((lane >> 4) & 1) * 8;
    const uint32_t b_k8   = ((lane >> 3) & 1) * 8;

    float acc[4][8][4];
#pragma unroll
    for (int i = 0; i < 4; ++i)
#pragma unroll
        for (int j = 0; j < 8; ++j)
#pragma unroll
            for (int q = 0; q < 4; ++q) acc[i][j][q] = 0.f;

    load_stage(0, 0);
    load_stage(1, 32);

    for (int it = 0; it < niter; ++it) {
        if (it + 1 < niter) cp_wait<1>(); else cp_wait<0>();
        __syncthreads();
        if (it + 2 < niter) load_stage((it + 2) % 3, (it + 2) * 32);

        const uint32_t sb = smb + 2 * (uint32_t)((it % 3) * STG);
#pragma unroll
        for (int ks = 0; ks < 2; ++ks) {
            uint32_t af[4][4], bf[8][2];
#pragma unroll
            for (int i = 0; i < 4; ++i) {
                uint32_t off = (a_row + i * 16) * RS + (ks * 16 + a_col);
                ldm_x4(sb + 2 * off, af[i][0], af[i][1], af[i][2], af[i][3]);
            }
#pragma unroll
            for (int jj = 0; jj < 4; ++jj) {
                uint32_t off = PART + (b_row2 + jj * 16) * RS + (ks * 16 + b_k8);
                ldm_x4(sb + 2 * off, bf[2*jj][0], bf[2*jj][1], bf[2*jj+1][0], bf[2*jj+1][1]);
            }
#pragma unroll
            for (int i = 0; i < 4; ++i)
#pragma unroll
                for (int j = 0; j < 8; ++j)
                    mma16816(acc[i][j], af[i], bf[j]);
        }
    }

    // ---- epilogue ----
    if (POOL) {
        // masked ragged column-sum: relu(v+bias) summed over valid rows
        const int b0 = m0 / Wn_;
        const int mbound = (b0 + 1) * Wn_;
        const int v0 = __ldg(lengths + b0) - 4;
        const int v1 = (b0 + 1 < B_) ? (__ldg(lengths + b0 + 1) - 4) : 0;
#pragma unroll
        for (int i = 0; i < 4; ++i) {
            const int rA = m0 + wm * 64 + i * 16 + (lane >> 2);
            const int rB = rA + 8;
            const int sA = (rA >= mbound), sB = (rB >= mbound);
            const int wA = rA - (sA ? mbound : b0 * Wn_);
            const int wB = rB - (sB ? mbound : b0 * Wn_);
            const bool okA = wA < (sA ? v1 : v0);
            const bool okB = wB < (sB ? v1 : v0);
#pragma unroll
            for (int j = 0; j < 8; ++j) {
                const int c0 = wn * 64 + j * 8 + (lane & 3) * 2;  // local col (n0=0)
                const float bz0 = __ldg(bias + c0), bz1 = __ldg(bias + c0 + 1);
                if (okA) {
                    float u0 = fmaxf(acc[i][j][0] + bz0, 0.f);
                    float u1 = fmaxf(acc[i][j][1] + bz1, 0.f);
                    atomicAdd(&sacc[sA][c0], u0);
                    atomicAdd(&sacc[sA][c0 + 1], u1);
                }
                if (okB) {
                    float u0 = fmaxf(acc[i][j][2] + bz0, 0.f);
                    float u1 = fmaxf(acc[i][j][3] + bz1, 0.f);
                    atomicAdd(&sacc[sB][c0], u0);
                    atomicAdd(&sacc[sB][c0 + 1], u1);
                }
            }
        }
        __syncthreads();
        if (tid < 128) {
            float a0 = sacc[0][tid];
            if (a0 != 0.f) atomicAdd(&g_pool[b0 * H2_ + tid], a0);
            if (mbound < m0 + 128 && b0 + 1 < B_) {
                float a1 = sacc[1][tid];
                if (a1 != 0.f) atomicAdd(&g_pool[(b0 + 1) * H2_ + tid], a1);
            }
        }
    } else {
#pragma unroll
        for (int i = 0; i < 4; ++i) {
            const int r0 = m0 + wm * 64 + i * 16 + (lane >> 2);
#pragma unroll
            for (int j = 0; j < 8; ++j) {
                const int c0 = n0 + wn * 64 + j * 8 + (lane & 3) * 2;
                const float bz0 = __ldg(bias + c0), bz1 = __ldg(bias + c0 + 1);
                float v00 = acc[i][j][0] + bz0, v01 = acc[i][j][1] + bz1;
                float v10 = acc[i][j][2] + bz0, v11 = acc[i][j][3] + bz1;
                if (relu) {
                    v00 = fmaxf(v00, 0.f); v01 = fmaxf(v01, 0.f);
                    v10 = fmaxf(v10, 0.f); v11 = fmaxf(v11, 0.f);
                }
                __half2 hp0, hp1;
                hp0.x = __float2half_rn(v00); hp0.y = __float2half_rn(v01);
                hp1.x = __float2half_rn(v10); hp1.y = __float2half_rn(v11);
                *(__half2*)(Ch + (size_t)r0 * Nn + c0)       = hp0;
                *(__half2*)(Ch + (size_t)(r0 + 8) * Nn + c0) = hp1;
            }
        }
    }
}

// ---------------- finalize: divide by valid count ----------------
__global__ void __launch_bounds__(128)
finalize(const int* __restrict__ lengths, float* __restrict__ out) {
    const int b = blockIdx.x, h = threadIdx.x;
    const int valid = lengths[b] - 4;
    out[b * H2_ + h] = g_pool[b * H2_ + h] / (float)valid;
}

// ---------------- launch ----------------
extern "C" void kernel_launch(void* const* d_in, const int* in_sizes, int n_in,
                              void* d_out, int out_size)
{
    const int*   x       = (const int*)  d_in[0];
    const int*   lengths = (const int*)  d_in[1];
    const float* table   = (const float*)d_in[2];
    const float* Wsl     = (const float*)d_in[3];
    const float* bsl     = (const float*)d_in[4];
    const float* W1      = (const float*)d_in[5];
    const float* b1      = (const float*)d_in[6];
    const float* W2      = (const float*)d_in[7];
    const float* b2      = (const float*)d_in[8];
    float*       out     = (float*)d_out;

    __half *embp, *w0p, *w1p, *w2p, *h0p, *h1p;
    cudaGetSymbolAddress((void**)&embp, g_emb);
    cudaGetSymbolAddress((void**)&w0p, g_w0);
    cudaGetSymbolAddress((void**)&w1p, g_w1);
    cudaGetSymbolAddress((void**)&w2p, g_w2);
    cudaGetSymbolAddress((void**)&h0p, g_h0);
    cudaGetSymbolAddress((void**)&h1p, g_h1);

    const int SMEM = 3 * (2 * 128 * 40) * 2;   // 61440 B per CTA, 2 CTAs/SM
    cudaFuncSetAttribute((void*)gemm_hmma<true,  false>, cudaFuncAttributeMaxDynamicSharedMemorySize, SMEM);
    cudaFuncSetAttribute((void*)gemm_hmma<false, false>, cudaFuncAttributeMaxDynamicSharedMemorySize, SMEM);
    cudaFuncSetAttribute((void*)gemm_hmma<false, true>,  cudaFuncAttributeMaxDynamicSharedMemorySize, SMEM);

    // prep
    {
        int total = (B_ * S_ + 8) * E_;
        prep_emb<<<(total + 255) / 256, 256>>>(x, table);
    }
    prep_w<<<(H0_ * K0P + 255) / 256, 256>>>(Wsl, w0p, 1500, K0P, H0_);
    prep_w<<<(H1_ * H0_ + 255) / 256, 256>>>(W1, w1p, H0_, H0_, H1_);
    prep_w<<<(H2_ * H1_ + 255) / 256, 256>>>(W2, w2p, H1_, H1_, H2_);
    zero_pool<<<(B_ * H2_ + 255) / 256, 256>>>();

    // layer 0: [65280 x 1536] (window view) x [1536 x 512]
    gemm_hmma<true, false><<<dim3(M_ / 128, H0_ / 128), 128, SMEM>>>(
        embp, w0p, bsl, nullptr, h0p, K0P, H0_, 0);
    // layer 1: relu([65280 x 512] x [512 x 256])
    gemm_hmma<false, false><<<dim3(M_ / 128, H1_ / 128), 128, SMEM>>>(
        h0p, w1p, b1, nullptr, h1p, H0_, H1_, 1);
    // layer 2: relu([65280 x 256] x [256 x 128]) fused with ragged pooling
    gemm_hmma<false, true><<<dim3(M_ / 128, 1), 128, SMEM>>>(
        h1p, w2p, b2, lengths, nullptr, H1_, H2_, 1);

    // finalize: mean
    finalize<<<B_, 128>>>(lengths, out);
}